// round 9
// baseline (speedup 1.0000x reference)
#include <cuda_runtime.h>
#include <cuda_bf16.h>
#include <math.h>

#define VOCAB 128000
#define NROWS 256
#define TPB   512
#define NBINS 4096
#define CAND  2048

typedef unsigned long long ull;

// unnormalized softmax weight; identical instruction sequence everywhere
__device__ __forceinline__ float comp_e(float l, float invt, float negxm) {
    return __expf(__fmaf_rn(l, invt, negxm));
}

// monotone bin on float bits of e (e in [0, ~1]); 32 bins per mantissa octave
__device__ __forceinline__ int bin_of_bits(unsigned eb) {
    return (int)(eb >> 18);
}

// JAX threefry2x32, 20 rounds, key = (0, 1)
__device__ __forceinline__ void threefry01(unsigned& x0, unsigned& x1) {
    const unsigned k0 = 0u, k1 = 1u, k2 = 0x1BD11BDAu ^ k0 ^ k1;
    x0 += k0; x1 += k1;
#define TFR(r) { x0 += x1; x1 = (x1 << (r)) | (x1 >> (32 - (r))); x1 ^= x0; }
    TFR(13) TFR(15) TFR(26) TFR(6)
    x0 += k1; x1 += k2 + 1u;
    TFR(17) TFR(29) TFR(16) TFR(24)
    x0 += k2; x1 += k0 + 2u;
    TFR(13) TFR(15) TFR(26) TFR(6)
    x0 += k0; x1 += k1 + 3u;
    TFR(17) TFR(29) TFR(16) TFR(24)
    x0 += k1; x1 += k2 + 4u;
    TFR(13) TFR(15) TFR(26) TFR(6)
    x0 += k2; x1 += k0 + 5u;
#undef TFR
}

// JAX partitionable threefry random_bits(32): counter=(0, b*V+v), fold = x0^x1
__device__ __forceinline__ unsigned noise_bits(int row, int v) {
    unsigned x0 = 0u;
    unsigned x1 = (unsigned)row * (unsigned)VOCAB + (unsigned)v;
    threefry01(x0, x1);
    return x0 ^ x1;
}

__device__ __forceinline__ float noise_of(unsigned bits) {
    float u = __uint_as_float((bits >> 9) | 0x3F800000u) - 1.0f;
    return fmaxf(-log1pf(-u), 1e-10f);
}

// =============================================================================
// One CTA per row: full pipeline, writes out[row] as FLOAT32.
// =============================================================================
__global__ __launch_bounds__(TPB) void sampler_kernel(const float* __restrict__ logits,
                                                      const float* __restrict__ temps,
                                                      const float* __restrict__ topps,
                                                      float* __restrict__ out)
{
    __shared__ float    s_hist[NBINS];   // 16KB
    __shared__ ull      s_keys[CAND];    // 16KB
    __shared__ float    s_f[TPB];
    __shared__ int      s_i[TPB];
    __shared__ double   s_d[TPB];
    __shared__ ull      s_u[TPB];
    __shared__ float    s_m;
    __shared__ int      s_greedy, s_cnt, s_binstar;
    __shared__ unsigned s_esb;
    __shared__ int      s_is;
    __shared__ double   s_cd;

    const int row  = blockIdx.x;
    const int tid  = threadIdx.x;
    const float* L = logits + (size_t)row * VOCAB;

    // ---- sweep 1: max + first argmax ---------------------------------------
    float bm = -INFINITY; int bi = 0x7FFFFFFF;
    for (int v = tid; v < VOCAB; v += TPB) {
        float x = L[v];
        if (x > bm) { bm = x; bi = v; }
    }
    s_f[tid] = bm; s_i[tid] = bi;
    __syncthreads();
    for (int off = TPB >> 1; off > 0; off >>= 1) {
        if (tid < off) {
            float o = s_f[tid + off]; int oi = s_i[tid + off];
            if (o > s_f[tid] || (o == s_f[tid] && oi < s_i[tid])) {
                s_f[tid] = o; s_i[tid] = oi;
            }
        }
        __syncthreads();
    }
    if (tid == 0) {
        s_m = s_f[0]; s_greedy = s_i[0]; s_cnt = 0;
        s_esb = 0u; s_is = 0x7FFFFFFF;     // default: keep everything
        s_binstar = -1;
    }
    __syncthreads();

    const float m      = s_m;
    const int   greedy = s_greedy;
    const float temp   = temps[row];
    const float t      = fmaxf(temp, 1e-5f);
    const float invt   = __frcp_rn(t);
    const float negxm  = -__fmul_rn(m, invt);

    // ---- sweep 2: Z (Kahan f32) + mass histogram over e-bits ---------------
    for (int i = tid; i < NBINS; i += TPB) s_hist[i] = 0.0f;
    __syncthreads();
    {
        float zs = 0.0f, zc = 0.0f;
        for (int v = tid; v < VOCAB; v += TPB) {
            float e = comp_e(L[v], invt, negxm);
            unsigned eb = __float_as_uint(e);
            if (eb != 0u) {
                float y = e - zc; float t2 = zs + y; zc = (t2 - zs) - y; zs = t2;
                atomicAdd(&s_hist[bin_of_bits(eb)], e);
            }
        }
        s_d[tid] = (double)zs - (double)zc;
    }
    __syncthreads();
    for (int off = TPB >> 1; off > 0; off >>= 1) {
        if (tid < off) s_d[tid] += s_d[tid + off];
        __syncthreads();
    }
    if (tid == 0) {
        double Zd = s_d[0];
        double cd = (double)topps[row] * Zd;
        s_cd = cd;
        double cum = 0.0;
        for (int b = NBINS - 1; b >= 0; b--) {
            cum += (double)s_hist[b];
            if (cum > cd) { s_binstar = b; break; }
        }
    }
    __syncthreads();
    const int    binstar = s_binstar;
    const double cd      = s_cd;

    if (binstar >= 0) {
        // ---- sweep 3: exact above-bin mass (Kahan) + n_hi + gather ----------
        float zs = 0.0f, zc = 0.0f; int nh = 0;
        for (int v = tid; v < VOCAB; v += TPB) {
            float e = comp_e(L[v], invt, negxm);
            unsigned eb = __float_as_uint(e);
            if (eb != 0u) {
                int b = bin_of_bits(eb);
                if (b > binstar) {
                    float y = e - zc; float t2 = zs + y; zc = (t2 - zs) - y; zs = t2;
                    nh++;
                } else if (b == binstar) {
                    int pos = atomicAdd(&s_cnt, 1);
                    if (pos < CAND)
                        s_keys[pos] = ((ull)(~eb) << 32) | (ull)(unsigned)v;
                }
            }
        }
        s_d[tid] = (double)zs - (double)zc;
        s_i[tid] = nh;
        __syncthreads();
        for (int off = TPB >> 1; off > 0; off >>= 1) {
            if (tid < off) { s_d[tid] += s_d[tid + off]; s_i[tid] += s_i[tid + off]; }
            __syncthreads();
        }
        const double zhi  = s_d[0];
        const int    n_hi = s_i[0];
        const int    n    = min(s_cnt, CAND);
        __syncthreads();

        if (s_cnt > CAND) {
            // overflow: keep whole bin (rare; tiny over-inclusion)
            if (tid == 0) { s_esb = (unsigned)binstar << 18; s_is = 0x7FFFFFFF; }
        } else {
            for (int i = tid; i < CAND; i += TPB)
                if (i >= n) s_keys[i] = 0xFFFFFFFFFFFFFFFFull;
            __syncthreads();

            // bitonic sort ascending on (~ebits, v)  =>  e desc, v asc
            for (int kk = 2; kk <= CAND; kk <<= 1) {
                for (int j = kk >> 1; j > 0; j >>= 1) {
                    for (int i = tid; i < CAND; i += TPB) {
                        int ixj = i ^ j;
                        if (ixj > i) {
                            ull a = s_keys[i], b2 = s_keys[ixj];
                            bool up = ((i & kk) == 0);
                            if ((a > b2) == up) { s_keys[i] = b2; s_keys[ixj] = a; }
                        }
                    }
                    __syncthreads();
                }
            }

            // serial exact scan (n <= 2048): K = last rank with cum <= cd
            if (tid == 0) {
                double cum = zhi; int K = -1;
                for (int i = 0; i < n; i++) {
                    unsigned eb = ~(unsigned)(s_keys[i] >> 32);
                    cum += (double)__uint_as_float(eb);
                    if (cum <= cd) K = i; else break;
                }
                if (K < 0 && n_hi == 0) K = 0;     // global rank 0 always kept
                if (K >= 0) {
                    ull key = s_keys[K];
                    s_esb = ~(unsigned)(key >> 32);
                    s_is  = (int)(unsigned)(key & 0xFFFFFFFFull);
                } else if (n > 0) {
                    // nothing in bin kept: kept = strictly above the bin
                    ull key = s_keys[0];
                    s_esb = ~(unsigned)(key >> 32);
                    s_is  = -1;
                }
            }
        }
    }
    __syncthreads();

    const unsigned esb = s_esb;
    const int      is  = s_is;

    // ---- sweep 4: exponential race ------------------------------------------
    ull best = 0ull;
    for (int v = tid; v < VOCAB; v += TPB) {
        float e = comp_e(L[v], invt, negxm);
        unsigned eb = __float_as_uint(e);
        bool kept = (eb > esb) || (eb == esb && v <= is) || (v == greedy);
        if (__any_sync(0xFFFFFFFFu, kept)) {
            if (kept) {
                float nz = noise_of(noise_bits(row, v));
                float sc = e / nz;
                ull pk = ((ull)__float_as_uint(sc) << 32) | (ull)(~(unsigned)v);
                if (pk > best) best = pk;
            }
        }
    }
    s_u[tid] = best;
    __syncthreads();
    for (int off = TPB >> 1; off > 0; off >>= 1) {
        if (tid < off) { ull o = s_u[tid + off]; if (o > s_u[tid]) s_u[tid] = o; }
        __syncthreads();
    }
    if (tid == 0) {
        int idx = (int)(~(unsigned)(s_u[0] & 0xFFFFFFFFull));
        int tok = (temp <= 1e-10f) ? greedy : idx;
        out[row] = (float)tok;          // OUTPUT IS FLOAT32
    }
}

extern "C" void kernel_launch(void* const* d_in, const int* in_sizes, int n_in,
                              void* d_out, int out_size) {
    const float* logits = (const float*)d_in[0];
    const float* temps  = (const float*)d_in[1];
    const float* topps  = (const float*)d_in[2];
    sampler_kernel<<<NROWS, TPB>>>(logits, temps, topps, (float*)d_out);
}

// round 10
// speedup vs baseline: 1.7141x; 1.7141x over previous
#include <cuda_runtime.h>
#include <cuda_bf16.h>
#include <math.h>

#define VOCAB  128000
#define NROWS  256
#define CSPLIT 16
#define SLICE  (VOCAB / CSPLIT)   /* 8000 */
#define S4     (SLICE / 4)        /* 2000 float4 */
#define NBINS  4096
#define CAND   2048
#define T1     256
#define T5     512

typedef unsigned long long ull;

// ---------------- device-global scratch --------------------------------------
__device__ ull    g_pmax[NROWS][CSPLIT];
__device__ float  g_hist[NROWS][NBINS];      // 4MB
__device__ double g_Z[NROWS];
__device__ float  g_invt[NROWS], g_negxm[NROWS];
__device__ int    g_binstar[NROWS];
__device__ double g_cd[NROWS];
__device__ double g_zhi[NROWS];
__device__ int    g_nhi[NROWS];
__device__ int    g_cnt[NROWS];
__device__ ull    g_cand[NROWS][CAND];       // 4MB
__device__ ull    g_best[NROWS];

// ---------------- helpers (identical expressions across kernels) -------------
__device__ __forceinline__ float comp_e(float l, float invt, float negxm) {
    return __expf(__fmaf_rn(l, invt, negxm));
}
__device__ __forceinline__ unsigned ordbits(float f) {
    unsigned u = __float_as_uint(f);
    return (u & 0x80000000u) ? ~u : (u | 0x80000000u);
}
__device__ __forceinline__ float unordbits(unsigned u) {
    unsigned b = (u & 0x80000000u) ? (u & 0x7FFFFFFFu) : ~u;
    return __uint_as_float(b);
}

// JAX threefry2x32, 20 rounds, key = (0, 1)
__device__ __forceinline__ void threefry01(unsigned& x0, unsigned& x1) {
    const unsigned k0 = 0u, k1 = 1u, k2 = 0x1BD11BDAu ^ k0 ^ k1;
    x0 += k0; x1 += k1;
#define TFR(r) { x0 += x1; x1 = __funnelshift_l(x1, x1, (r)); x1 ^= x0; }
    TFR(13) TFR(15) TFR(26) TFR(6)
    x0 += k1; x1 += k2 + 1u;
    TFR(17) TFR(29) TFR(16) TFR(24)
    x0 += k2; x1 += k0 + 2u;
    TFR(13) TFR(15) TFR(26) TFR(6)
    x0 += k0; x1 += k1 + 3u;
    TFR(17) TFR(29) TFR(16) TFR(24)
    x0 += k1; x1 += k2 + 4u;
    TFR(13) TFR(15) TFR(26) TFR(6)
    x0 += k2; x1 += k0 + 5u;
#undef TFR
}
// partitionable random_bits(32): counter = (0, b*V+v), fold = x0 ^ x1
__device__ __forceinline__ unsigned noise_bits(int row, int v) {
    unsigned x0 = 0u;
    unsigned x1 = (unsigned)row * (unsigned)VOCAB + (unsigned)v;
    threefry01(x0, x1);
    return x0 ^ x1;
}
__device__ __forceinline__ float noise_of(unsigned bits) {
    float u = __uint_as_float((bits >> 9) | 0x3F800000u) - 1.0f;
    return fmaxf(-log1pf(-u), 1e-10f);
}
__device__ __forceinline__ ull race_pack(float e, int row, int v) {
    float nz = noise_of(noise_bits(row, v));
    float sc = e / nz;
    return ((ull)__float_as_uint(sc) << 32) | (ull)(unsigned)(~(unsigned)v);
}

// =============================================================================
// K1: partial max/argmax per (slice, row) + scratch zeroing
// =============================================================================
__global__ __launch_bounds__(T1) void k1_max(const float* __restrict__ logits)
{
    __shared__ ull s[T1];
    const int row = blockIdx.y, c = blockIdx.x, tid = threadIdx.x;
    const float4* L4 = reinterpret_cast<const float4*>(
        logits + (size_t)row * VOCAB + (size_t)c * SLICE);

    float bm = -INFINITY; int bi = 0;
    for (int i = tid; i < S4; i += T1) {
        float4 q = L4[i];
        int b = c * SLICE + 4 * i;
        if (q.x > bm) { bm = q.x; bi = b; }
        if (q.y > bm) { bm = q.y; bi = b + 1; }
        if (q.z > bm) { bm = q.z; bi = b + 2; }
        if (q.w > bm) { bm = q.w; bi = b + 3; }
    }
    s[tid] = ((ull)ordbits(bm) << 32) | (ull)(unsigned)(~(unsigned)bi);
    __syncthreads();
    for (int o = T1 >> 1; o > 0; o >>= 1) {
        if (tid < o && s[tid + o] > s[tid]) s[tid] = s[tid + o];
        __syncthreads();
    }
    if (tid == 0) g_pmax[row][c] = s[0];

    // zero scratch (each CTA owns NBINS/CSPLIT = 256 bins; T1 = 256)
    g_hist[row][c * (NBINS / CSPLIT) + tid] = 0.0f;
    if (tid == 0 && c == 0) {
        g_cnt[row] = 0; g_nhi[row] = 0; g_best[row] = 0ull;
        g_zhi[row] = 0.0; g_Z[row] = 0.0;
    }
}

// =============================================================================
// K2: Z (Kahan + double) + e-bits mass histogram
// =============================================================================
__global__ __launch_bounds__(T1) void k2_zhist(const float* __restrict__ logits,
                                               const float* __restrict__ temps)
{
    __shared__ float  sh[NBINS];    // 16KB
    __shared__ ull    sp[CSPLIT];
    __shared__ double sd[T1];
    const int row = blockIdx.y, c = blockIdx.x, tid = threadIdx.x;

    if (tid < CSPLIT) sp[tid] = g_pmax[row][tid];
    for (int i = tid; i < NBINS; i += T1) sh[i] = 0.0f;
    __syncthreads();

    ull k = sp[0];
    #pragma unroll
    for (int j = 1; j < CSPLIT; j++) if (sp[j] > k) k = sp[j];
    const float m     = unordbits((unsigned)(k >> 32));
    const float temp  = temps[row];
    const float t     = fmaxf(temp, 1e-5f);
    const float invt  = __frcp_rn(t);
    const float negxm = -__fmul_rn(m, invt);
    if (c == 0 && tid == 0) { g_invt[row] = invt; g_negxm[row] = negxm; }

    const float4* L4 = reinterpret_cast<const float4*>(
        logits + (size_t)row * VOCAB + (size_t)c * SLICE);
    float zs = 0.0f, zc = 0.0f;
    for (int i = tid; i < S4; i += T1) {
        float4 q = L4[i];
        float ls[4] = { q.x, q.y, q.z, q.w };
        #pragma unroll
        for (int j = 0; j < 4; j++) {
            float e = comp_e(ls[j], invt, negxm);
            unsigned eb = __float_as_uint(e);
            if (eb != 0u) {
                float y = e - zc; float t2 = zs + y; zc = (t2 - zs) - y; zs = t2;
                atomicAdd(&sh[eb >> 18], e);
            }
        }
    }
    sd[tid] = (double)zs - (double)zc;
    __syncthreads();
    for (int o = T1 >> 1; o > 0; o >>= 1) {
        if (tid < o) sd[tid] += sd[tid + o];
        __syncthreads();
    }
    if (tid == 0) atomicAdd(&g_Z[row], sd[0]);
    for (int b = tid; b < NBINS; b += T1) {
        float v = sh[b];
        if (v != 0.0f) atomicAdd(&g_hist[row][b], v);
    }
}

// =============================================================================
// K3: per-row suffix scan of histogram -> cutoff bin + cd
// =============================================================================
__global__ __launch_bounds__(T1) void k3_scan(const float* __restrict__ topps)
{
    __shared__ double sc[T1];
    __shared__ int    s_r;
    const int row = blockIdx.x, tid = threadIdx.x;
    if (tid == 0) s_r = 0x7FFFFFFF;
    __syncthreads();

    double loc[16]; double part = 0.0;
    #pragma unroll
    for (int j = 0; j < 16; j++) {
        int r = tid * 16 + j;                 // reversed rank; bin = NBINS-1-r
        part += (double)g_hist[row][NBINS - 1 - r];
        loc[j] = part;
    }
    sc[tid] = part;
    __syncthreads();
    for (int off = 1; off < T1; off <<= 1) {
        double add = (tid >= off) ? sc[tid - off] : 0.0;
        __syncthreads();
        sc[tid] += add;
        __syncthreads();
    }
    const double cd   = (double)topps[row] * g_Z[row];
    const double base = (tid > 0) ? sc[tid - 1] : 0.0;
    #pragma unroll
    for (int j = 0; j < 16; j++) {
        if (base + loc[j] > cd) { atomicMin(&s_r, tid * 16 + j); break; }
    }
    __syncthreads();
    if (tid == 0) {
        g_binstar[row] = (s_r == 0x7FFFFFFF) ? -1 : (NBINS - 1 - s_r);
        g_cd[row] = cd;
    }
}

// =============================================================================
// K4: gather cutoff-bin candidates + exponential race over sure-kept tokens
// =============================================================================
__global__ __launch_bounds__(T1) void k4_gather(const float* __restrict__ logits)
{
    __shared__ ull    sb[T1];
    __shared__ double sd[T1];
    __shared__ int    si[T1];
    const int row = blockIdx.y, c = blockIdx.x, tid = threadIdx.x;
    const int binstar = g_binstar[row];
    const float invt = g_invt[row], negxm = g_negxm[row];
    const float4* L4 = reinterpret_cast<const float4*>(
        logits + (size_t)row * VOCAB + (size_t)c * SLICE);

    ull best = 0ull; float zs = 0.0f, zc = 0.0f; int nh = 0;
    for (int i = tid; i < S4; i += T1) {
        float4 q = L4[i];
        float ls[4] = { q.x, q.y, q.z, q.w };
        #pragma unroll
        for (int j = 0; j < 4; j++) {
            float e = comp_e(ls[j], invt, negxm);
            unsigned eb = __float_as_uint(e);
            if (eb == 0u) continue;            // zero prob: can never win
            int b = (int)(eb >> 18);
            if (b > binstar) {
                float y = e - zc; float t2 = zs + y; zc = (t2 - zs) - y; zs = t2;
                nh++;
                int v = c * SLICE + 4 * i + j;
                ull pk = race_pack(e, row, v);
                if (pk > best) best = pk;
            } else if (b == binstar) {
                int v = c * SLICE + 4 * i + j;
                int pos = atomicAdd(&g_cnt[row], 1);
                if (pos < CAND)
                    g_cand[row][pos] = ((ull)(~eb) << 32) | (ull)(unsigned)v;
            }
        }
    }
    sb[tid] = best; sd[tid] = (double)zs - (double)zc; si[tid] = nh;
    __syncthreads();
    for (int o = T1 >> 1; o > 0; o >>= 1) {
        if (tid < o) {
            if (sb[tid + o] > sb[tid]) sb[tid] = sb[tid + o];
            sd[tid] += sd[tid + o];
            si[tid] += si[tid + o];
        }
        __syncthreads();
    }
    if (tid == 0) {
        if (sb[0]) atomicMax(&g_best[row], sb[0]);
        atomicAdd(&g_zhi[row], sd[0]);
        atomicAdd(&g_nhi[row], si[0]);
    }
}

// =============================================================================
// K5: sort candidates, exact threshold, race kept candidates, finalize out[row]
// =============================================================================
__global__ __launch_bounds__(T5) void k5_final(const float* __restrict__ temps,
                                               float* __restrict__ out)
{
    __shared__ ull keys[CAND];     // 16KB
    __shared__ ull su[T5];
    __shared__ ull sp[CSPLIT];
    __shared__ int s_K;
    const int row = blockIdx.x, tid = threadIdx.x;

    if (tid < CSPLIT) sp[tid] = g_pmax[row][tid];
    const int n = min(g_cnt[row], CAND);
    for (int i = tid; i < CAND; i += T5)
        keys[i] = (i < n) ? g_cand[row][i] : 0xFFFFFFFFFFFFFFFFull;
    __syncthreads();

    if (n > 0) {
        // bitonic sort ascending on (~ebits, v) => e desc, v asc
        for (int kk = 2; kk <= CAND; kk <<= 1) {
            for (int j = kk >> 1; j > 0; j >>= 1) {
                for (int i = tid; i < CAND; i += T5) {
                    int ixj = i ^ j;
                    if (ixj > i) {
                        ull a = keys[i], b2 = keys[ixj];
                        bool up = ((i & kk) == 0);
                        if ((a > b2) == up) { keys[i] = b2; keys[ixj] = a; }
                    }
                }
                __syncthreads();
            }
        }
    }
    if (tid == 0) {
        int K = -1;
        if (n > 0) {
            if (g_cnt[row] > CAND) {
                K = n - 1;                       // overflow fallback: keep stored bin
            } else {
                double cum = g_zhi[row];
                const double cd = g_cd[row];
                for (int i = 0; i < n; i++) {
                    unsigned eb = ~(unsigned)(keys[i] >> 32);
                    cum += (double)__uint_as_float(eb);
                    if (cum <= cd) K = i; else break;
                }
                if (K < 0 && g_nhi[row] == 0) K = 0;  // global rank 0 always kept
            }
        }
        s_K = K;
    }
    __syncthreads();
    const int K = s_K;

    ull best = (tid == 0) ? g_best[row] : 0ull;
    for (int i = tid; i <= K; i += T5) {
        ull key = keys[i];
        unsigned eb = ~(unsigned)(key >> 32);
        int v = (int)(unsigned)(key & 0xFFFFFFFFull);
        ull pk = race_pack(__uint_as_float(eb), row, v);
        if (pk > best) best = pk;
    }
    su[tid] = best;
    __syncthreads();
    for (int o = T5 >> 1; o > 0; o >>= 1) {
        if (tid < o && su[tid + o] > su[tid]) su[tid] = su[tid + o];
        __syncthreads();
    }
    if (tid == 0) {
        ull k = sp[0];
        #pragma unroll
        for (int j = 1; j < CSPLIT; j++) if (sp[j] > k) k = sp[j];
        int greedy = (int)(~(unsigned)(k & 0xFFFFFFFFull));
        int winner = (int)(~(unsigned)(su[0] & 0xFFFFFFFFull));
        float temp = temps[row];
        out[row] = (float)((temp <= 1e-10f) ? greedy : winner);
    }
}

extern "C" void kernel_launch(void* const* d_in, const int* in_sizes, int n_in,
                              void* d_out, int out_size) {
    const float* logits = (const float*)d_in[0];
    const float* temps  = (const float*)d_in[1];
    const float* topps  = (const float*)d_in[2];
    float* out = (float*)d_out;

    dim3 gs(CSPLIT, NROWS);
    k1_max   <<<gs,    T1>>>(logits);
    k2_zhist <<<gs,    T1>>>(logits, temps);
    k3_scan  <<<NROWS, T1>>>(topps);
    k4_gather<<<gs,    T1>>>(logits);
    k5_final <<<NROWS, T5>>>(temps, out);
}